// round 9
// baseline (speedup 1.0000x reference)
#include <cuda_runtime.h>
#include <cstdint>

#define N_NODES 50000
#define N_EDGES 800000
#define NB 444          // 148 SMs x 3 resident blocks (GB300 has 152 -> slack)
#define NTH 256
#define NCH 391         // scan chunks of 128 nodes
#define NTILE 782       // GEMM tiles of 64 nodes

typedef unsigned long long ull;

// ---------------- device globals (no allocation allowed) --------------------
__device__ int   g_deg[N_NODES];
__device__ int   g_off[N_NODES + 1];
__device__ int   g_cur[N_NODES];
__device__ int   g_bsum[NCH];
__device__ int   g_esrc[N_EDGES];
__device__ float g_mean[(size_t)N_NODES * 96];
__device__ float g_h1[(size_t)N_NODES * 96];
__device__ float g_y[(size_t)N_NODES * 96];     // [yl(48) | yr(48)]
__device__ unsigned g_tick;                     // ticket barrier counter

__device__ __forceinline__ int clampN(int v) {
    return v < 0 ? 0 : (v >= N_NODES ? N_NODES - 1 : v);
}

// ---- packed f32x2 (FFMA2 via PTX) -------------------------------------------
__device__ __forceinline__ ull pack2(float x, float y) {
    ull r; asm("mov.b64 %0, {%1, %2};" : "=l"(r) : "f"(x), "f"(y)); return r;
}
__device__ __forceinline__ ull fma2(ull a, ull b, ull c) {
    ull d; asm("fma.rn.f32x2 %0, %1, %2, %3;" : "=l"(d) : "l"(a), "l"(b), "l"(c)); return d;
}
__device__ __forceinline__ float2 unpack2(ull v) {
    float2 f; asm("mov.b64 {%0, %1}, %2;" : "=f"(f.x), "=f"(f.y) : "l"(v)); return f;
}

// ---- grid barrier: ticket scheme, replay-safe (no resets) -------------------
__device__ __forceinline__ void gbar() {
    __syncthreads();
    if (threadIdx.x == 0) {
        __threadfence();                          // release + L1 invalidate
        unsigned t = atomicAdd(&g_tick, 1u);
        unsigned target = (t / NB + 1u) * NB;
        while ((int)(atomicAdd(&g_tick, 0u) - target) < 0) __nanosleep(64);
        __threadfence();                          // acquire + L1 invalidate
    }
    __syncthreads();
}

// ---- aggregation phase: warp per node, strided ------------------------------
__device__ void agg_phase(const float* __restrict__ hin) {
    int gw   = (blockIdx.x * NTH + threadIdx.x) >> 5;
    int lane = threadIdx.x & 31;
    const int stride = (NB * NTH) >> 5;
    for (int w = gw; w < N_NODES; w += stride) {
        int beg = g_off[w], end = g_off[w + 1];
        float a0 = 0.f, a1 = 0.f, a2 = 0.f;
        int e = beg;
        for (; e + 3 < end; e += 4) {
            const float* r0 = hin + (size_t)g_esrc[e]     * 96;
            const float* r1 = hin + (size_t)g_esrc[e + 1] * 96;
            const float* r2 = hin + (size_t)g_esrc[e + 2] * 96;
            const float* r3 = hin + (size_t)g_esrc[e + 3] * 96;
            a0 += (r0[lane]      + r1[lane])      + (r2[lane]      + r3[lane]);
            a1 += (r0[lane + 32] + r1[lane + 32]) + (r2[lane + 32] + r3[lane + 32]);
            a2 += (r0[lane + 64] + r1[lane + 64]) + (r2[lane + 64] + r3[lane + 64]);
        }
        for (; e < end; e++) {
            const float* r0 = hin + (size_t)g_esrc[e] * 96;
            a0 += r0[lane]; a1 += r0[lane + 32]; a2 += r0[lane + 64];
        }
        int deg = end - beg;
        float inv = 1.0f / (float)(deg > 0 ? deg : 1);
        float* o = g_mean + (size_t)w * 96;
        o[lane] = a0 * inv; o[lane + 32] = a1 * inv; o[lane + 64] = a2 * inv;
    }
}

// ---- dual-GEMM tile loop (layers 0): out = relu(mean@Wl + h@Wr + b) ---------
__device__ void gemm_dual(const float* __restrict__ hin,
                          const float* __restrict__ Wl, const float* __restrict__ Wr,
                          const float* __restrict__ bias, float* __restrict__ outp,
                          float* sm) {
    float* sWl = sm;            // [32][96]
    float* sWr = sm + 3072;     // [32][96]
    float* sM  = sm + 6144;     // [64][33]
    float* sH  = sM + 64 * 33;  // [64][33]

    int tid = threadIdx.x;
    int jg = tid & 7, ig = tid >> 3;     // 8 col groups x 32 row groups
    int j0 = jg * 12;

    for (int t = blockIdx.x; t < NTILE; t += NB) {
        int node0 = t * 64;
        ull acc[2][6];
        #pragma unroll
        for (int r = 0; r < 2; r++)
            #pragma unroll
            for (int p = 0; p < 6; p++) acc[r][p] = 0ull;

        for (int kc = 0; kc < 96; kc += 32) {
            __syncthreads();
            for (int idx = tid; idx < 32 * 24; idx += NTH) {
                int kk = idx / 24, j4 = idx % 24;
                float4 vl = *(const float4*)&Wl[(kc + kk) * 96 + j4 * 4];
                float4 vr = *(const float4*)&Wr[(kc + kk) * 96 + j4 * 4];
                *(float4*)&sWl[kk * 96 + j4 * 4] = vl;
                *(float4*)&sWr[kk * 96 + j4 * 4] = vr;
            }
            for (int idx = tid; idx < 64 * 8; idx += NTH) {
                int ii = idx >> 3, q = idx & 7;
                int row = clampN(node0 + ii);
                size_t base = (size_t)row * 96 + kc + q * 4;
                float4 m = *(const float4*)&g_mean[base];
                float4 h = *(const float4*)&hin[base];
                sM[ii*33+q*4+0]=m.x; sM[ii*33+q*4+1]=m.y; sM[ii*33+q*4+2]=m.z; sM[ii*33+q*4+3]=m.w;
                sH[ii*33+q*4+0]=h.x; sH[ii*33+q*4+1]=h.y; sH[ii*33+q*4+2]=h.z; sH[ii*33+q*4+3]=h.w;
            }
            __syncthreads();

            #pragma unroll 2
            for (int k = 0; k < 32; k++) {
                ull wl[6], wr[6];
                #pragma unroll
                for (int p = 0; p < 6; p++) {
                    float2 l = *(const float2*)&sWl[k * 96 + j0 + 2 * p];
                    float2 r = *(const float2*)&sWr[k * 96 + j0 + 2 * p];
                    wl[p] = pack2(l.x, l.y); wr[p] = pack2(r.x, r.y);
                }
                #pragma unroll
                for (int r = 0; r < 2; r++) {
                    int row = ig * 2 + r;
                    ull m2 = pack2(sM[row * 33 + k], sM[row * 33 + k]);
                    ull h2 = pack2(sH[row * 33 + k], sH[row * 33 + k]);
                    #pragma unroll
                    for (int p = 0; p < 6; p++)
                        acc[r][p] = fma2(m2, wl[p], fma2(h2, wr[p], acc[r][p]));
                }
            }
        }

        #pragma unroll
        for (int r = 0; r < 2; r++) {
            int node = node0 + ig * 2 + r;
            if (node < N_NODES) {
                float* o = outp + (size_t)node * 96 + j0;
                #pragma unroll
                for (int p = 0; p < 6; p++) {
                    float2 v = unpack2(acc[r][p]);
                    float2 b = *(const float2*)&bias[j0 + 2 * p];
                    float2 s;
                    s.x = fmaxf(v.x + b.x, 0.f);
                    s.y = fmaxf(v.y + b.y, 0.f);
                    *(float2*)&o[2 * p] = s;
                }
            }
        }
    }
}

// ---- fused layer1+layer2: h2 = relu(mean@Wl1 + h1@Wr1 + b1) kept in smem,
//      then g_y = [h2@Wl2 | h2@Wr2 + b2]  ------------------------------------
__device__ void gemm_fused(const float* __restrict__ h1,
                           const float* __restrict__ Wl1, const float* __restrict__ Wr1,
                           const float* __restrict__ b1,
                           const float* __restrict__ Wl2, const float* __restrict__ Wr2,
                           const float* __restrict__ b2, float* sm) {
    float* sWl = sm;
    float* sWr = sm + 3072;
    float* sM  = sm + 6144;      // [64][33]  (phase A)
    float* sH  = sM + 64 * 33;
    float* h2b = sm + 6144;      // [64][98]  (phase B, overlays sM/sH)

    int tid = threadIdx.x;
    int jg = tid & 7, ig = tid >> 3;
    int j0 = jg * 12;

    for (int t = blockIdx.x; t < NTILE; t += NB) {
        int node0 = t * 64;
        ull acc[2][6];
        #pragma unroll
        for (int r = 0; r < 2; r++)
            #pragma unroll
            for (int p = 0; p < 6; p++) acc[r][p] = 0ull;

        // ---- phase A: dual GEMM for h2 ----
        for (int kc = 0; kc < 96; kc += 32) {
            __syncthreads();
            for (int idx = tid; idx < 32 * 24; idx += NTH) {
                int kk = idx / 24, j4 = idx % 24;
                float4 vl = *(const float4*)&Wl1[(kc + kk) * 96 + j4 * 4];
                float4 vr = *(const float4*)&Wr1[(kc + kk) * 96 + j4 * 4];
                *(float4*)&sWl[kk * 96 + j4 * 4] = vl;
                *(float4*)&sWr[kk * 96 + j4 * 4] = vr;
            }
            for (int idx = tid; idx < 64 * 8; idx += NTH) {
                int ii = idx >> 3, q = idx & 7;
                int row = clampN(node0 + ii);
                size_t base = (size_t)row * 96 + kc + q * 4;
                float4 m = *(const float4*)&g_mean[base];
                float4 h = *(const float4*)&h1[base];
                sM[ii*33+q*4+0]=m.x; sM[ii*33+q*4+1]=m.y; sM[ii*33+q*4+2]=m.z; sM[ii*33+q*4+3]=m.w;
                sH[ii*33+q*4+0]=h.x; sH[ii*33+q*4+1]=h.y; sH[ii*33+q*4+2]=h.z; sH[ii*33+q*4+3]=h.w;
            }
            __syncthreads();

            #pragma unroll 2
            for (int k = 0; k < 32; k++) {
                ull wl[6], wr[6];
                #pragma unroll
                for (int p = 0; p < 6; p++) {
                    float2 l = *(const float2*)&sWl[k * 96 + j0 + 2 * p];
                    float2 r = *(const float2*)&sWr[k * 96 + j0 + 2 * p];
                    wl[p] = pack2(l.x, l.y); wr[p] = pack2(r.x, r.y);
                }
                #pragma unroll
                for (int r = 0; r < 2; r++) {
                    int row = ig * 2 + r;
                    ull m2 = pack2(sM[row * 33 + k], sM[row * 33 + k]);
                    ull h2 = pack2(sH[row * 33 + k], sH[row * 33 + k]);
                    #pragma unroll
                    for (int p = 0; p < 6; p++)
                        acc[r][p] = fma2(m2, wl[p], fma2(h2, wr[p], acc[r][p]));
                }
            }
        }

        // ---- h2 = relu(acc + b1) -> smem (overlays sM/sH) ----
        __syncthreads();
        #pragma unroll
        for (int r = 0; r < 2; r++) {
            int row = ig * 2 + r;
            #pragma unroll
            for (int p = 0; p < 6; p++) {
                float2 v = unpack2(acc[r][p]);
                float2 b = *(const float2*)&b1[j0 + 2 * p];
                float2 s;
                s.x = fmaxf(v.x + b.x, 0.f);
                s.y = fmaxf(v.y + b.y, 0.f);
                *(float2*)&h2b[row * 98 + j0 + 2 * p] = s;
            }
            #pragma unroll
            for (int p = 0; p < 6; p++) acc[r][p] = 0ull;
        }

        // ---- phase B: g_y tile = [h2@Wl2 | h2@Wr2 + b2] ----
        for (int kc = 0; kc < 96; kc += 32) {
            __syncthreads();
            for (int idx = tid; idx < 32 * 24; idx += NTH) {
                int kk = idx / 24, j4 = idx % 24;
                int j = j4 * 4;
                float4 v = (j < 48) ? *(const float4*)&Wl2[(kc + kk) * 48 + j]
                                    : *(const float4*)&Wr2[(kc + kk) * 48 + (j - 48)];
                *(float4*)&sWl[kk * 96 + j] = v;
            }
            __syncthreads();

            #pragma unroll 2
            for (int k = 0; k < 32; k++) {
                ull w[6];
                #pragma unroll
                for (int p = 0; p < 6; p++) {
                    float2 l = *(const float2*)&sWl[k * 96 + j0 + 2 * p];
                    w[p] = pack2(l.x, l.y);
                }
                #pragma unroll
                for (int r = 0; r < 2; r++) {
                    float hv = h2b[(ig * 2 + r) * 98 + kc + k];
                    ull h2 = pack2(hv, hv);
                    #pragma unroll
                    for (int p = 0; p < 6; p++)
                        acc[r][p] = fma2(h2, w[p], acc[r][p]);
                }
            }
        }

        #pragma unroll
        for (int r = 0; r < 2; r++) {
            int node = node0 + ig * 2 + r;
            if (node < N_NODES) {
                float* o = g_y + (size_t)node * 96 + j0;
                #pragma unroll
                for (int p = 0; p < 6; p++) {
                    float2 v = unpack2(acc[r][p]);
                    int c = j0 + 2 * p;
                    if (c >= 48) { v.x += b2[c - 48]; v.y += b2[c - 47]; }
                    *(float2*)&o[2 * p] = v;
                }
            }
        }
    }
}

// ---- final 48-wide aggregation + relu ---------------------------------------
__device__ void agg48_phase(float* __restrict__ out) {
    int gw   = (blockIdx.x * NTH + threadIdx.x) >> 5;
    int lane = threadIdx.x & 31;
    const int stride = (NB * NTH) >> 5;
    for (int w = gw; w < N_NODES; w += stride) {
        int beg = g_off[w], end = g_off[w + 1];
        float a0 = 0.f, a1 = 0.f, b0 = 0.f, b1 = 0.f;
        int e = beg;
        for (; e + 7 < end; e += 8) {
            const float* r0 = g_y + (size_t)g_esrc[e]     * 96;
            const float* r1 = g_y + (size_t)g_esrc[e + 1] * 96;
            const float* r2 = g_y + (size_t)g_esrc[e + 2] * 96;
            const float* r3 = g_y + (size_t)g_esrc[e + 3] * 96;
            const float* r4 = g_y + (size_t)g_esrc[e + 4] * 96;
            const float* r5 = g_y + (size_t)g_esrc[e + 5] * 96;
            const float* r6 = g_y + (size_t)g_esrc[e + 6] * 96;
            const float* r7 = g_y + (size_t)g_esrc[e + 7] * 96;
            a0 += (r0[lane] + r1[lane]) + (r2[lane] + r3[lane]);
            b0 += (r4[lane] + r5[lane]) + (r6[lane] + r7[lane]);
            if (lane < 16) {
                a1 += (r0[32+lane] + r1[32+lane]) + (r2[32+lane] + r3[32+lane]);
                b1 += (r4[32+lane] + r5[32+lane]) + (r6[32+lane] + r7[32+lane]);
            }
        }
        for (; e < end; e++) {
            const float* r0 = g_y + (size_t)g_esrc[e] * 96;
            a0 += r0[lane];
            if (lane < 16) a1 += r0[32 + lane];
        }
        a0 += b0; a1 += b1;
        int deg = end - beg;
        float inv = 1.0f / (float)(deg > 0 ? deg : 1);
        const float* yr = g_y + (size_t)w * 96 + 48;
        float* o = out + (size_t)w * 48;
        o[lane] = fmaxf(a0 * inv + yr[lane], 0.f);
        if (lane < 16) o[32 + lane] = fmaxf(a1 * inv + yr[32 + lane], 0.f);
    }
}

// ---------------- the persistent kernel --------------------------------------
__global__ void __launch_bounds__(NTH, 3) k_all(
    const float* __restrict__ x, const int* __restrict__ ei,
    const float* __restrict__ Wl0, const float* __restrict__ Wr0, const float* __restrict__ b0,
    const float* __restrict__ Wl1, const float* __restrict__ Wr1, const float* __restrict__ b1,
    const float* __restrict__ Wl2, const float* __restrict__ Wr2, const float* __restrict__ b2,
    float* __restrict__ out)
{
    extern __shared__ __align__(16) float sm[];
    int* smi = (int*)sm;
    int tid = threadIdx.x, bid = blockIdx.x;

    // P0: zero degrees
    for (int i = bid * NTH + tid; i < N_NODES; i += NB * NTH) g_deg[i] = 0;
    gbar();

    // P1: count in-degrees
    for (int e = bid * NTH + tid; e < N_EDGES; e += NB * NTH)
        atomicAdd(&g_deg[clampN(ei[N_EDGES + e])], 1);
    gbar();

    // P2a: chunk sums (128 nodes per chunk)
    if (bid < NCH) {
        int i = bid * 128 + tid;
        if (tid < 128) smi[tid] = (i < N_NODES) ? g_deg[i] : 0;
        __syncthreads();
        for (int s = 64; s > 0; s >>= 1) {
            if (tid < s) smi[tid] += smi[tid + s];
            __syncthreads();
        }
        if (tid == 0) g_bsum[bid] = smi[0];
    }
    gbar();

    // P2b: scan chunk sums (block 0, serial in smem)
    if (bid == 0) {
        for (int i = tid; i < NCH; i += NTH) smi[i] = g_bsum[i];
        __syncthreads();
        if (tid == 0) {
            int a = 0;
            for (int i = 0; i < NCH; i++) { int t = smi[i]; smi[i] = a; a += t; }
        }
        __syncthreads();
        for (int i = tid; i < NCH; i += NTH) g_bsum[i] = smi[i];
    }
    gbar();

    // P2c: local exclusive scan + base
    if (bid < NCH) {
        int i = bid * 128 + tid;
        int v = (tid < 128 && i < N_NODES) ? g_deg[i] : 0;
        if (tid < 128) smi[tid] = v;
        __syncthreads();
        for (int d = 1; d < 128; d <<= 1) {
            int t = (tid < 128 && tid >= d) ? smi[tid - d] : 0;
            __syncthreads();
            if (tid < 128) smi[tid] += t;
            __syncthreads();
        }
        if (tid < 128 && i < N_NODES) {
            int o = g_bsum[bid] + smi[tid] - v;
            g_off[i] = o; g_cur[i] = o;
        }
        if (bid == 0 && tid == 0) g_off[N_NODES] = N_EDGES;
    }
    gbar();

    // P3: fill CSR
    for (int e = bid * NTH + tid; e < N_EDGES; e += NB * NTH) {
        int s = clampN(ei[e]);
        int d = clampN(ei[N_EDGES + e]);
        int p = atomicAdd(&g_cur[d], 1);
        if (p >= 0 && p < N_EDGES) g_esrc[p] = s;
    }
    gbar();

    // P4: agg0: x -> g_mean
    agg_phase(x);
    gbar();

    // P5: gemm0: (g_mean, x) -> g_h1
    gemm_dual(x, Wl0, Wr0, b0, g_h1, sm);
    gbar();

    // P6: agg1: g_h1 -> g_mean
    agg_phase(g_h1);
    gbar();

    // P7: gemm1 (+fused layer-2 projection) -> g_y
    gemm_fused(g_h1, Wl1, Wr1, b1, Wl2, Wr2, b2, sm);
    gbar();

    // P8: final 48-wide aggregation -> out
    agg48_phase(out);
}

// ---------------- launch ------------------------------------------------------
extern "C" void kernel_launch(void* const* d_in, const int* in_sizes, int n_in,
                              void* d_out, int out_size)
{
    const float* x   = (const float*)d_in[0];
    const int*   ei  = (const int*)d_in[1];     // int32 (JAX x64 disabled)
    const float* Wl0 = (const float*)d_in[2];
    const float* Wr0 = (const float*)d_in[3];
    const float* b0  = (const float*)d_in[4];
    const float* Wl1 = (const float*)d_in[5];
    const float* Wr1 = (const float*)d_in[6];
    const float* b1  = (const float*)d_in[7];
    const float* Wl2 = (const float*)d_in[8];
    const float* Wr2 = (const float*)d_in[9];
    const float* b2  = (const float*)d_in[10];
    float*       out = (float*)d_out;

    // smem: weights 6144 floats + max(sM+sH = 64*33*2, h2b = 64*98) floats
    constexpr int SMEM = (6144 + 64 * 98) * 4;   // 49,664 B
    cudaFuncSetAttribute(k_all, cudaFuncAttributeMaxDynamicSharedMemorySize, SMEM);

    k_all<<<NB, NTH, SMEM>>>(x, ei, Wl0, Wr0, b0, Wl1, Wr1, b1, Wl2, Wr2, b2, out);
}

// round 10
// speedup vs baseline: 1.0635x; 1.0635x over previous
#include <cuda_runtime.h>
#include <cstdint>

#define N_NODES 50000
#define N_EDGES 800000

typedef unsigned long long ull;

// ---------------- device globals (no allocation allowed) --------------------
__device__ int   g_deg[N_NODES];
__device__ int   g_off[N_NODES + 1];
__device__ int   g_cur[N_NODES];
__device__ int   g_bsum[64];
__device__ int   g_esrc[N_EDGES];
__device__ float g_mean[(size_t)N_NODES * 96];
__device__ float g_h1[(size_t)N_NODES * 96];
__device__ float g_yr[(size_t)N_NODES * 96];    // right-term GEMM results
__device__ float g_y[(size_t)N_NODES * 96];     // layer2 projection [yl48|yr48]

__device__ __forceinline__ int clampN(int v) {
    return v < 0 ? 0 : (v >= N_NODES ? N_NODES - 1 : v);
}

// ---- packed f32x2 (FFMA2 via PTX) -------------------------------------------
__device__ __forceinline__ ull pack2(float x, float y) {
    ull r; asm("mov.b64 %0, {%1, %2};" : "=l"(r) : "f"(x), "f"(y)); return r;
}
__device__ __forceinline__ ull fma2(ull a, ull b, ull c) {
    ull d; asm("fma.rn.f32x2 %0, %1, %2, %3;" : "=l"(d) : "l"(a), "l"(b), "l"(c)); return d;
}
__device__ __forceinline__ float2 unpack2(ull v) {
    float2 f; asm("mov.b64 {%0, %1}, %2;" : "=f"(f.x), "=f"(f.y) : "l"(v)); return f;
}

// ---------------- CSR build ----------------------------------------------------
__global__ void k_zero() {
    int i = blockIdx.x * blockDim.x + threadIdx.x;
    if (i < N_NODES) g_deg[i] = 0;
}
__global__ void k_scan1() {
    __shared__ int s[1024];
    int i = blockIdx.x * 1024 + threadIdx.x;
    int v = (i < N_NODES) ? g_deg[i] : 0;
    s[threadIdx.x] = v;
    __syncthreads();
    for (int d = 1; d < 1024; d <<= 1) {
        int t = (threadIdx.x >= d) ? s[threadIdx.x - d] : 0;
        __syncthreads();
        s[threadIdx.x] += t;
        __syncthreads();
    }
    if (i < N_NODES) g_off[i] = s[threadIdx.x] - v;
    if (threadIdx.x == 1023) g_bsum[blockIdx.x] = s[1023];
}
__global__ void k_scan3() {
    __shared__ int sb[64];
    __shared__ int base;
    int t = threadIdx.x;
    if (t < 64) sb[t] = (t < blockIdx.x) ? g_bsum[t] : 0;
    __syncthreads();
    if (t == 0) {
        int a = 0;
        #pragma unroll
        for (int b = 0; b < 64; b++) a += sb[b];
        base = a;
    }
    __syncthreads();
    int i = blockIdx.x * 1024 + t;
    if (i < N_NODES) { int o = g_off[i] + base; g_off[i] = o; g_cur[i] = o; }
    if (i == 0) g_off[N_NODES] = N_EDGES;
}
__global__ void k_fill(const int* __restrict__ ei) {
    int e = blockIdx.x * blockDim.x + threadIdx.x;
    if (e < N_EDGES) {
        int s = clampN(ei[e]);
        int d = clampN(ei[N_EDGES + e]);
        int p = atomicAdd(&g_cur[d], 1);
        if (p >= 0 && p < N_EDGES) g_esrc[p] = s;
    }
}

// ---- 96-wide mean aggregation for one 8-node chunk (8 warps) ------------------
__device__ __forceinline__ void agg_chunk(int c, const float* __restrict__ hin) {
    int wid  = threadIdx.x >> 5;
    int lane = threadIdx.x & 31;
    int w = c * 8 + wid;
    if (w >= N_NODES) return;
    int beg = g_off[w], end = g_off[w + 1];
    float a0 = 0.f, a1 = 0.f, a2 = 0.f;
    int e = beg;
    for (; e + 3 < end; e += 4) {
        const float* r0 = hin + (size_t)g_esrc[e]     * 96;
        const float* r1 = hin + (size_t)g_esrc[e + 1] * 96;
        const float* r2 = hin + (size_t)g_esrc[e + 2] * 96;
        const float* r3 = hin + (size_t)g_esrc[e + 3] * 96;
        a0 += (r0[lane]      + r1[lane])      + (r2[lane]      + r3[lane]);
        a1 += (r0[lane + 32] + r1[lane + 32]) + (r2[lane + 32] + r3[lane + 32]);
        a2 += (r0[lane + 64] + r1[lane + 64]) + (r2[lane + 64] + r3[lane + 64]);
    }
    for (; e < end; e++) {
        const float* r0 = hin + (size_t)g_esrc[e] * 96;
        a0 += r0[lane]; a1 += r0[lane + 32]; a2 += r0[lane + 64];
    }
    int deg = end - beg;
    float inv = 1.0f / (float)(deg > 0 ? deg : 1);
    float* o = g_mean + (size_t)w * 96;
    o[lane] = a0 * inv; o[lane + 32] = a1 * inv; o[lane + 64] = a2 * inv;
}

// ---- single-input GEMM tile: out[n][:] = in[n][:]@W + b -----------------------
__device__ __forceinline__ void gemm_si_tile(
    int tile, const float* __restrict__ in, const float* __restrict__ W,
    const float* __restrict__ bias, float* __restrict__ outp,
    float* sW, float* sA)
{
    int tid = threadIdx.x;
    int jg = tid & 7, ig = tid >> 3;
    int j0 = jg * 12;
    int node0 = tile * 64;

    ull acc[2][6];
    #pragma unroll
    for (int r = 0; r < 2; r++)
        #pragma unroll
        for (int p = 0; p < 6; p++) acc[r][p] = 0ull;

    for (int kc = 0; kc < 96; kc += 32) {
        __syncthreads();
        for (int idx = tid; idx < 32 * 24; idx += 256) {
            int kk = idx / 24, j4 = idx % 24;
            *(float4*)&sW[kk * 96 + j4 * 4] = *(const float4*)&W[(kc + kk) * 96 + j4 * 4];
        }
        for (int idx = tid; idx < 64 * 8; idx += 256) {
            int ii = idx >> 3, q = idx & 7;
            int row = clampN(node0 + ii);
            float4 v = *(const float4*)&in[(size_t)row * 96 + kc + q * 4];
            sA[ii*33+q*4+0]=v.x; sA[ii*33+q*4+1]=v.y; sA[ii*33+q*4+2]=v.z; sA[ii*33+q*4+3]=v.w;
        }
        __syncthreads();

        #pragma unroll 2
        for (int k = 0; k < 32; k++) {
            ull w[6];
            #pragma unroll
            for (int p = 0; p < 6; p++) {
                float2 l = *(const float2*)&sW[k * 96 + j0 + 2 * p];
                w[p] = pack2(l.x, l.y);
            }
            #pragma unroll
            for (int r = 0; r < 2; r++) {
                float av = sA[(ig * 2 + r) * 33 + k];
                ull a2 = pack2(av, av);
                #pragma unroll
                for (int p = 0; p < 6; p++)
                    acc[r][p] = fma2(a2, w[p], acc[r][p]);
            }
        }
    }

    #pragma unroll
    for (int r = 0; r < 2; r++) {
        int node = node0 + ig * 2 + r;
        if (node < N_NODES) {
            float* o = outp + (size_t)node * 96 + j0;
            #pragma unroll
            for (int p = 0; p < 6; p++) {
                float2 v = unpack2(acc[r][p]);
                float2 b = *(const float2*)&bias[j0 + 2 * p];
                v.x += b.x; v.y += b.y;
                *(float2*)&o[2 * p] = v;
            }
        }
    }
}

// ---- K1: edge count (4/5) interleaved with gemmR0 = x@Wr0 + b0 (1/5) ----------
__global__ void __launch_bounds__(256) k_count_gemmR0(
    const int* __restrict__ ei, const float* __restrict__ x,
    const float* __restrict__ Wr0, const float* __restrict__ b0)
{
    __shared__ float sW[32 * 96];
    __shared__ float sA[64 * 33];
    int bid = blockIdx.x;
    int g = bid / 5, r = bid % 5;
    if (r == 4) {
        gemm_si_tile(g, x, Wr0, b0, g_yr, sW, sA);
    } else {
        int c = g * 4 + r;
        int e = c * 256 + threadIdx.x;
        if (c < 3125 && e < N_EDGES)
            atomicAdd(&g_deg[clampN(ei[N_EDGES + e])], 1);
    }
}

// ---- gemmL0: g_h1 = relu(mean@Wl0 + yr0) --------------------------------------
__global__ void __launch_bounds__(256) k_gemmL0(const float* __restrict__ Wl0) {
    __shared__ float sW[32 * 96];
    __shared__ float sA[64 * 33];
    int tid = threadIdx.x;
    int jg = tid & 7, ig = tid >> 3;
    int j0 = jg * 12;
    int node0 = blockIdx.x * 64;

    ull acc[2][6];
    #pragma unroll
    for (int r = 0; r < 2; r++)
        #pragma unroll
        for (int p = 0; p < 6; p++) acc[r][p] = 0ull;

    for (int kc = 0; kc < 96; kc += 32) {
        __syncthreads();
        for (int idx = tid; idx < 32 * 24; idx += 256) {
            int kk = idx / 24, j4 = idx % 24;
            *(float4*)&sW[kk * 96 + j4 * 4] = *(const float4*)&Wl0[(kc + kk) * 96 + j4 * 4];
        }
        for (int idx = tid; idx < 64 * 8; idx += 256) {
            int ii = idx >> 3, q = idx & 7;
            int row = clampN(node0 + ii);
            float4 v = *(const float4*)&g_mean[(size_t)row * 96 + kc + q * 4];
            sA[ii*33+q*4+0]=v.x; sA[ii*33+q*4+1]=v.y; sA[ii*33+q*4+2]=v.z; sA[ii*33+q*4+3]=v.w;
        }
        __syncthreads();

        #pragma unroll 2
        for (int k = 0; k < 32; k++) {
            ull w[6];
            #pragma unroll
            for (int p = 0; p < 6; p++) {
                float2 l = *(const float2*)&sW[k * 96 + j0 + 2 * p];
                w[p] = pack2(l.x, l.y);
            }
            #pragma unroll
            for (int r = 0; r < 2; r++) {
                float av = sA[(ig * 2 + r) * 33 + k];
                ull a2 = pack2(av, av);
                #pragma unroll
                for (int p = 0; p < 6; p++)
                    acc[r][p] = fma2(a2, w[p], acc[r][p]);
            }
        }
    }

    #pragma unroll
    for (int r = 0; r < 2; r++) {
        int node = node0 + ig * 2 + r;
        if (node < N_NODES) {
            const float* yr = g_yr + (size_t)node * 96 + j0;
            float* o = g_h1 + (size_t)node * 96 + j0;
            #pragma unroll
            for (int p = 0; p < 6; p++) {
                float2 v = unpack2(acc[r][p]);
                float2 y = *(const float2*)&yr[2 * p];
                float2 s;
                s.x = fmaxf(v.x + y.x, 0.f);
                s.y = fmaxf(v.y + y.y, 0.f);
                *(float2*)&o[2 * p] = s;
            }
        }
    }
}

// ---- K7: agg1 (8/9) interleaved with gemmR1 = h1@Wr1 + b1 (1/9) ---------------
__global__ void __launch_bounds__(256) k_agg_gemmR1(
    const float* __restrict__ Wr1, const float* __restrict__ b1)
{
    __shared__ float sW[32 * 96];
    __shared__ float sA[64 * 33];
    int bid = blockIdx.x;
    int g = bid / 9, r = bid % 9;
    if (r == 8) {
        gemm_si_tile(g, g_h1, Wr1, b1, g_yr, sW, sA);
    } else {
        int c = g * 8 + r;
        if (c < 6250) agg_chunk(c, g_h1);
    }
}

// ---- K8: h2 = relu(mean@Wl1 + yr1) in smem, then g_y = [h2@Wl2 | h2@Wr2+b2] ---
__global__ void __launch_bounds__(256) k_gemmL1_proj(
    const float* __restrict__ Wl1,
    const float* __restrict__ Wl2, const float* __restrict__ Wr2,
    const float* __restrict__ b2)
{
    __shared__ float sW[32 * 96];
    __shared__ float sA[64 * 33];
    __shared__ float h2b[64 * 98];
    int tid = threadIdx.x;
    int jg = tid & 7, ig = tid >> 3;
    int j0 = jg * 12;
    int node0 = blockIdx.x * 64;

    ull acc[2][6];
    #pragma unroll
    for (int r = 0; r < 2; r++)
        #pragma unroll
        for (int p = 0; p < 6; p++) acc[r][p] = 0ull;

    for (int kc = 0; kc < 96; kc += 32) {
        __syncthreads();
        for (int idx = tid; idx < 32 * 24; idx += 256) {
            int kk = idx / 24, j4 = idx % 24;
            *(float4*)&sW[kk * 96 + j4 * 4] = *(const float4*)&Wl1[(kc + kk) * 96 + j4 * 4];
        }
        for (int idx = tid; idx < 64 * 8; idx += 256) {
            int ii = idx >> 3, q = idx & 7;
            int row = clampN(node0 + ii);
            float4 v = *(const float4*)&g_mean[(size_t)row * 96 + kc + q * 4];
            sA[ii*33+q*4+0]=v.x; sA[ii*33+q*4+1]=v.y; sA[ii*33+q*4+2]=v.z; sA[ii*33+q*4+3]=v.w;
        }
        __syncthreads();

        #pragma unroll 2
        for (int k = 0; k < 32; k++) {
            ull w[6];
            #pragma unroll
            for (int p = 0; p < 6; p++) {
                float2 l = *(const float2*)&sW[k * 96 + j0 + 2 * p];
                w[p] = pack2(l.x, l.y);
            }
            #pragma unroll
            for (int r = 0; r < 2; r++) {
                float av = sA[(ig * 2 + r) * 33 + k];
                ull a2 = pack2(av, av);
                #pragma unroll
                for (int p = 0; p < 6; p++)
                    acc[r][p] = fma2(a2, w[p], acc[r][p]);
            }
        }
    }

    __syncthreads();
    #pragma unroll
    for (int r = 0; r < 2; r++) {
        int row = ig * 2 + r;
        int node = clampN(node0 + row);
        const float* yr = g_yr + (size_t)node * 96 + j0;
        #pragma unroll
        for (int p = 0; p < 6; p++) {
            float2 v = unpack2(acc[r][p]);
            float2 y = *(const float2*)&yr[2 * p];
            float2 s;
            s.x = fmaxf(v.x + y.x, 0.f);
            s.y = fmaxf(v.y + y.y, 0.f);
            *(float2*)&h2b[row * 98 + j0 + 2 * p] = s;
        }
        #pragma unroll
        for (int p = 0; p < 6; p++) acc[r][p] = 0ull;
    }

    for (int kc = 0; kc < 96; kc += 32) {
        __syncthreads();
        for (int idx = tid; idx < 32 * 24; idx += 256) {
            int kk = idx / 24, j4 = idx % 24;
            int j = j4 * 4;
            float4 v = (j < 48) ? *(const float4*)&Wl2[(kc + kk) * 48 + j]
                                : *(const float4*)&Wr2[(kc + kk) * 48 + (j - 48)];
            *(float4*)&sW[kk * 96 + j] = v;
        }
        __syncthreads();

        #pragma unroll 2
        for (int k = 0; k < 32; k++) {
            ull w[6];
            #pragma unroll
            for (int p = 0; p < 6; p++) {
                float2 l = *(const float2*)&sW[k * 96 + j0 + 2 * p];
                w[p] = pack2(l.x, l.y);
            }
            #pragma unroll
            for (int r = 0; r < 2; r++) {
                float hv = h2b[(ig * 2 + r) * 98 + kc + k];
                ull a2 = pack2(hv, hv);
                #pragma unroll
                for (int p = 0; p < 6; p++)
                    acc[r][p] = fma2(a2, w[p], acc[r][p]);
            }
        }
    }

    #pragma unroll
    for (int r = 0; r < 2; r++) {
        int node = node0 + ig * 2 + r;
        if (node < N_NODES) {
            float* o = g_y + (size_t)node * 96 + j0;
            #pragma unroll
            for (int p = 0; p < 6; p++) {
                float2 v = unpack2(acc[r][p]);
                int c = j0 + 2 * p;
                if (c >= 48) { v.x += b2[c - 48]; v.y += b2[c - 47]; }
                *(float2*)&o[2 * p] = v;
            }
        }
    }
}

// ---- agg0 standalone (x -> g_mean) --------------------------------------------
__global__ void k_agg0(const float* __restrict__ x) {
    agg_chunk(blockIdx.x, x);
}

// ---- final 48-wide aggregation + relu ------------------------------------------
__global__ void k_agg48(float* __restrict__ out) {
    int w    = (blockIdx.x * blockDim.x + threadIdx.x) >> 5;
    int lane = threadIdx.x & 31;
    if (w >= N_NODES) return;
    int beg = g_off[w], end = g_off[w + 1];
    float a0 = 0.f, a1 = 0.f, b0 = 0.f, b1 = 0.f;
    int e = beg;
    for (; e + 7 < end; e += 8) {
        const float* r0 = g_y + (size_t)g_esrc[e]     * 96;
        const float* r1 = g_y + (size_t)g_esrc[e + 1] * 96;
        const float* r2 = g_y + (size_t)g_esrc[e + 2] * 96;
        const float* r3 = g_y + (size_t)g_esrc[e + 3] * 96;
        const float* r4 = g_y + (size_t)g_esrc[e + 4] * 96;
        const float* r5 = g_y + (size_t)g_esrc[e + 5] * 96;
        const float* r6 = g_y + (size_t)g_esrc[e + 6] * 96;
        const float* r7 = g_y + (size_t)g_esrc[e + 7] * 96;
        a0 += (r0[lane] + r1[lane]) + (r2[lane] + r3[lane]);
        b0 += (r4[lane] + r5[lane]) + (r6[lane] + r7[lane]);
        if (lane < 16) {
            a1 += (r0[32+lane] + r1[32+lane]) + (r2[32+lane] + r3[32+lane]);
            b1 += (r4[32+lane] + r5[32+lane]) + (r6[32+lane] + r7[32+lane]);
        }
    }
    for (; e < end; e++) {
        const float* r0 = g_y + (size_t)g_esrc[e] * 96;
        a0 += r0[lane];
        if (lane < 16) a1 += r0[32 + lane];
    }
    a0 += b0; a1 += b1;
    int deg = end - beg;
    float inv = 1.0f / (float)(deg > 0 ? deg : 1);
    const float* yr = g_y + (size_t)w * 96 + 48;
    float* o = out + (size_t)w * 48;
    o[lane] = fmaxf(a0 * inv + yr[lane], 0.f);
    if (lane < 16) o[32 + lane] = fmaxf(a1 * inv + yr[32 + lane], 0.f);
}

// ---------------- launch ---------------------------------------------------------
extern "C" void kernel_launch(void* const* d_in, const int* in_sizes, int n_in,
                              void* d_out, int out_size)
{
    const float* x   = (const float*)d_in[0];
    const int*   ei  = (const int*)d_in[1];     // int32 (JAX x64 disabled)
    const float* Wr0 = (const float*)d_in[3];
    const float* Wl0 = (const float*)d_in[2];
    const float* b0  = (const float*)d_in[4];
    const float* Wl1 = (const float*)d_in[5];
    const float* Wr1 = (const float*)d_in[6];
    const float* b1  = (const float*)d_in[7];
    const float* Wl2 = (const float*)d_in[8];
    const float* Wr2 = (const float*)d_in[9];
    const float* b2  = (const float*)d_in[10];
    float*       out = (float*)d_out;

    const int nScanBlk = (N_NODES + 1023) / 1024;   // 49
    const int nEdgeBlk = (N_EDGES + 255) / 256;     // 3125
    const int aggBlk   = (N_NODES + 7) / 8;         // 6250
    const int tileBlk  = (N_NODES + 63) / 64;       // 782

    k_zero<<<(N_NODES + 255) / 256, 256>>>();
    k_count_gemmR0<<<tileBlk * 5, 256>>>(ei, x, Wr0, b0);   // count ∥ gemmR0
    k_scan1<<<nScanBlk, 1024>>>();
    k_scan3<<<nScanBlk, 1024>>>();
    k_fill<<<nEdgeBlk, 256>>>(ei);

    k_agg0<<<aggBlk, 256>>>(x);                              // agg0
    k_gemmL0<<<tileBlk, 256>>>(Wl0);                         // h1 = relu(mean@Wl0 + yr0)
    k_agg_gemmR1<<<tileBlk * 9, 256>>>(Wr1, b1);             // agg1 ∥ gemmR1
    k_gemmL1_proj<<<tileBlk, 256>>>(Wl1, Wl2, Wr2, b2);      // h2 (smem) -> g_y
    k_agg48<<<aggBlk, 256>>>(out);                           // out
}

// round 11
// speedup vs baseline: 1.3928x; 1.3097x over previous
#include <cuda_runtime.h>
#include <cstdint>

#define N_NODES 50000
#define N_EDGES 800000

typedef unsigned long long ull;

// ---------------- device globals (no allocation allowed) --------------------
__device__ int   g_deg[N_NODES];
__device__ int   g_off[N_NODES + 1];
__device__ int   g_cur[N_NODES];
__device__ int   g_bsum[64];
__device__ int   g_esrc[N_EDGES];
__device__ float g_mean[(size_t)N_NODES * 96];
__device__ float g_h1[(size_t)N_NODES * 96];
__device__ float g_yr[(size_t)N_NODES * 96];    // right-term GEMM results
__device__ float g_y[(size_t)N_NODES * 96];     // layer2 projection [yl48|yr48]

__device__ __forceinline__ int clampN(int v) {
    return v < 0 ? 0 : (v >= N_NODES ? N_NODES - 1 : v);
}

// ---- packed f32x2 (FFMA2 via PTX) -------------------------------------------
__device__ __forceinline__ ull pack2(float x, float y) {
    ull r; asm("mov.b64 %0, {%1, %2};" : "=l"(r) : "f"(x), "f"(y)); return r;
}
__device__ __forceinline__ ull fma2(ull a, ull b, ull c) {
    ull d; asm("fma.rn.f32x2 %0, %1, %2, %3;" : "=l"(d) : "l"(a), "l"(b), "l"(c)); return d;
}
__device__ __forceinline__ float2 unpack2(ull v) {
    float2 f; asm("mov.b64 {%0, %1}, %2;" : "=f"(f.x), "=f"(f.y) : "l"(v)); return f;
}

// ---------------- CSR build (R8 verbatim) -------------------------------------
__global__ void k_zero() {
    int i = blockIdx.x * blockDim.x + threadIdx.x;
    if (i < N_NODES) g_deg[i] = 0;
}
__global__ void k_count(const int* __restrict__ ei) {
    int e = blockIdx.x * blockDim.x + threadIdx.x;
    if (e < N_EDGES) atomicAdd(&g_deg[clampN(ei[N_EDGES + e])], 1);
}
__global__ void k_scan1() {
    __shared__ int s[1024];
    int i = blockIdx.x * 1024 + threadIdx.x;
    int v = (i < N_NODES) ? g_deg[i] : 0;
    s[threadIdx.x] = v;
    __syncthreads();
    for (int d = 1; d < 1024; d <<= 1) {
        int t = (threadIdx.x >= d) ? s[threadIdx.x - d] : 0;
        __syncthreads();
        s[threadIdx.x] += t;
        __syncthreads();
    }
    if (i < N_NODES) g_off[i] = s[threadIdx.x] - v;
    if (threadIdx.x == 1023) g_bsum[blockIdx.x] = s[1023];
}
__global__ void k_scan3() {
    __shared__ int sb[64];
    __shared__ int base;
    int t = threadIdx.x;
    if (t < 64) sb[t] = (t < blockIdx.x) ? g_bsum[t] : 0;
    __syncthreads();
    if (t == 0) {
        int a = 0;
        #pragma unroll
        for (int b = 0; b < 64; b++) a += sb[b];
        base = a;
    }
    __syncthreads();
    int i = blockIdx.x * 1024 + t;
    if (i < N_NODES) { int o = g_off[i] + base; g_off[i] = o; g_cur[i] = o; }
    if (i == 0) g_off[N_NODES] = N_EDGES;
}
__global__ void k_fill(const int* __restrict__ ei) {
    int e = blockIdx.x * blockDim.x + threadIdx.x;
    if (e < N_EDGES) {
        int s = clampN(ei[e]);
        int d = clampN(ei[N_EDGES + e]);
        int p = atomicAdd(&g_cur[d], 1);
        if (p >= 0 && p < N_EDGES) g_esrc[p] = s;
    }
}

// ---------------- mean aggregation (96-wide), warp per node (R8) --------------
template <int SRC>  // 0 = ext(x), 1 = g_h1
__global__ void k_agg(const float* __restrict__ ext) {
    const float* hin = SRC == 1 ? g_h1 : ext;
    int w    = (blockIdx.x * blockDim.x + threadIdx.x) >> 5;
    int lane = threadIdx.x & 31;
    if (w >= N_NODES) return;
    int beg = g_off[w], end = g_off[w + 1];
    float a0 = 0.f, a1 = 0.f, a2 = 0.f;
    int e = beg;
    for (; e + 3 < end; e += 4) {
        const float* r0 = hin + (size_t)g_esrc[e]     * 96;
        const float* r1 = hin + (size_t)g_esrc[e + 1] * 96;
        const float* r2 = hin + (size_t)g_esrc[e + 2] * 96;
        const float* r3 = hin + (size_t)g_esrc[e + 3] * 96;
        a0 += (r0[lane]      + r1[lane])      + (r2[lane]      + r3[lane]);
        a1 += (r0[lane + 32] + r1[lane + 32]) + (r2[lane + 32] + r3[lane + 32]);
        a2 += (r0[lane + 64] + r1[lane + 64]) + (r2[lane + 64] + r3[lane + 64]);
    }
    for (; e < end; e++) {
        const float* r0 = hin + (size_t)g_esrc[e] * 96;
        a0 += r0[lane]; a1 += r0[lane + 32]; a2 += r0[lane + 64];
    }
    int deg = end - beg;
    float inv = 1.0f / (float)(deg > 0 ? deg : 1);
    float* o = g_mean + (size_t)w * 96;
    o[lane] = a0 * inv; o[lane + 32] = a1 * inv; o[lane + 64] = a2 * inv;
}

// ---- gemmR<L>: g_yr = in@Wr + b   (in: L=0 -> x, L=1 -> g_h1) -----------------
// R8 GEMM shape: 128 threads, TN=64, 4 rows x 12 cols per thread.
template <int L>
__global__ void __launch_bounds__(128) k_gemmR(
    const float* __restrict__ ext_in,
    const float* __restrict__ Wr, const float* __restrict__ bias)
{
    const float* in = (L == 0) ? ext_in : g_h1;
    constexpr int TN = 64, KC = 32;
    __shared__ float sW[KC][96];
    __shared__ float sA[TN][KC + 1];

    int tid = threadIdx.x;
    int jg = tid % 8, ig = tid / 8;
    int j0 = jg * 12;
    int node0 = blockIdx.x * TN;

    ull acc[4][6];
    #pragma unroll
    for (int r = 0; r < 4; r++)
        #pragma unroll
        for (int p = 0; p < 6; p++) acc[r][p] = 0ull;

    for (int kc = 0; kc < 96; kc += KC) {
        __syncthreads();
        #pragma unroll
        for (int idx = tid; idx < KC * 24; idx += 128) {
            int kk = idx / 24, j4 = idx % 24;
            *(float4*)&sW[kk][j4 * 4] = *(const float4*)&Wr[(kc + kk) * 96 + j4 * 4];
        }
        #pragma unroll
        for (int idx = tid; idx < TN * 8; idx += 128) {
            int ii = idx >> 3, q = idx & 7;
            int row = clampN(node0 + ii);
            float4 v = *(const float4*)&in[(size_t)row * 96 + kc + q * 4];
            sA[ii][q*4+0]=v.x; sA[ii][q*4+1]=v.y; sA[ii][q*4+2]=v.z; sA[ii][q*4+3]=v.w;
        }
        __syncthreads();

        #pragma unroll 2
        for (int k = 0; k < KC; k++) {
            ull w[6];
            #pragma unroll
            for (int p = 0; p < 6; p++) {
                float2 l = *(const float2*)&sW[k][j0 + 2 * p];
                w[p] = pack2(l.x, l.y);
            }
            #pragma unroll
            for (int r = 0; r < 4; r++) {
                float av = sA[ig * 4 + r][k];
                ull a2 = pack2(av, av);
                #pragma unroll
                for (int p = 0; p < 6; p++)
                    acc[r][p] = fma2(a2, w[p], acc[r][p]);
            }
        }
    }

    #pragma unroll
    for (int r = 0; r < 4; r++) {
        int node = node0 + ig * 4 + r;
        if (node < N_NODES) {
            float* o = g_yr + (size_t)node * 96 + j0;
            #pragma unroll
            for (int p = 0; p < 6; p++) {
                float2 v = unpack2(acc[r][p]);
                float2 b = *(const float2*)&bias[j0 + 2 * p];
                v.x += b.x; v.y += b.y;
                *(float2*)&o[2 * p] = v;
            }
        }
    }
}

// ---- gemmL0: g_h1 = relu(g_mean@Wl0 + g_yr) ----------------------------------
__global__ void __launch_bounds__(128) k_gemmL0(const float* __restrict__ Wl0) {
    constexpr int TN = 64, KC = 32;
    __shared__ float sW[KC][96];
    __shared__ float sA[TN][KC + 1];

    int tid = threadIdx.x;
    int jg = tid % 8, ig = tid / 8;
    int j0 = jg * 12;
    int node0 = blockIdx.x * TN;

    ull acc[4][6];
    #pragma unroll
    for (int r = 0; r < 4; r++)
        #pragma unroll
        for (int p = 0; p < 6; p++) acc[r][p] = 0ull;

    for (int kc = 0; kc < 96; kc += KC) {
        __syncthreads();
        #pragma unroll
        for (int idx = tid; idx < KC * 24; idx += 128) {
            int kk = idx / 24, j4 = idx % 24;
            *(float4*)&sW[kk][j4 * 4] = *(const float4*)&Wl0[(kc + kk) * 96 + j4 * 4];
        }
        #pragma unroll
        for (int idx = tid; idx < TN * 8; idx += 128) {
            int ii = idx >> 3, q = idx & 7;
            int row = clampN(node0 + ii);
            float4 v = *(const float4*)&g_mean[(size_t)row * 96 + kc + q * 4];
            sA[ii][q*4+0]=v.x; sA[ii][q*4+1]=v.y; sA[ii][q*4+2]=v.z; sA[ii][q*4+3]=v.w;
        }
        __syncthreads();

        #pragma unroll 2
        for (int k = 0; k < KC; k++) {
            ull w[6];
            #pragma unroll
            for (int p = 0; p < 6; p++) {
                float2 l = *(const float2*)&sW[k][j0 + 2 * p];
                w[p] = pack2(l.x, l.y);
            }
            #pragma unroll
            for (int r = 0; r < 4; r++) {
                float av = sA[ig * 4 + r][k];
                ull a2 = pack2(av, av);
                #pragma unroll
                for (int p = 0; p < 6; p++)
                    acc[r][p] = fma2(a2, w[p], acc[r][p]);
            }
        }
    }

    #pragma unroll
    for (int r = 0; r < 4; r++) {
        int node = node0 + ig * 4 + r;
        if (node < N_NODES) {
            const float* yr = g_yr + (size_t)node * 96 + j0;
            float* o = g_h1 + (size_t)node * 96 + j0;
            #pragma unroll
            for (int p = 0; p < 6; p++) {
                float2 v = unpack2(acc[r][p]);
                float2 y = *(const float2*)&yr[2 * p];
                float2 s;
                s.x = fmaxf(v.x + y.x, 0.f);
                s.y = fmaxf(v.y + y.y, 0.f);
                *(float2*)&o[2 * p] = s;
            }
        }
    }
}

// ---- gemmL1 + layer2 projection: h2 = relu(mean@Wl1 + yr1) in smem,
//      then g_y = [h2@Wl2 | h2@Wr2 + b2] ---------------------------------------
__global__ void __launch_bounds__(128) k_gemmL1_proj(
    const float* __restrict__ Wl1,
    const float* __restrict__ Wl2, const float* __restrict__ Wr2,
    const float* __restrict__ b2)
{
    constexpr int TN = 64, KC = 32;
    __shared__ float sW[KC][96];
    __shared__ float sA[TN][KC + 1];
    __shared__ float h2b[TN][98];

    int tid = threadIdx.x;
    int jg = tid % 8, ig = tid / 8;
    int j0 = jg * 12;
    int node0 = blockIdx.x * TN;

    ull acc[4][6];
    #pragma unroll
    for (int r = 0; r < 4; r++)
        #pragma unroll
        for (int p = 0; p < 6; p++) acc[r][p] = 0ull;

    // phase A: mean@Wl1
    for (int kc = 0; kc < 96; kc += KC) {
        __syncthreads();
        #pragma unroll
        for (int idx = tid; idx < KC * 24; idx += 128) {
            int kk = idx / 24, j4 = idx % 24;
            *(float4*)&sW[kk][j4 * 4] = *(const float4*)&Wl1[(kc + kk) * 96 + j4 * 4];
        }
        #pragma unroll
        for (int idx = tid; idx < TN * 8; idx += 128) {
            int ii = idx >> 3, q = idx & 7;
            int row = clampN(node0 + ii);
            float4 v = *(const float4*)&g_mean[(size_t)row * 96 + kc + q * 4];
            sA[ii][q*4+0]=v.x; sA[ii][q*4+1]=v.y; sA[ii][q*4+2]=v.z; sA[ii][q*4+3]=v.w;
        }
        __syncthreads();

        #pragma unroll 2
        for (int k = 0; k < KC; k++) {
            ull w[6];
            #pragma unroll
            for (int p = 0; p < 6; p++) {
                float2 l = *(const float2*)&sW[k][j0 + 2 * p];
                w[p] = pack2(l.x, l.y);
            }
            #pragma unroll
            for (int r = 0; r < 4; r++) {
                float av = sA[ig * 4 + r][k];
                ull a2 = pack2(av, av);
                #pragma unroll
                for (int p = 0; p < 6; p++)
                    acc[r][p] = fma2(a2, w[p], acc[r][p]);
            }
        }
    }

    // h2 = relu(acc + yr1) -> smem
    __syncthreads();
    #pragma unroll
    for (int r = 0; r < 4; r++) {
        int row = ig * 4 + r;
        int node = clampN(node0 + row);
        const float* yr = g_yr + (size_t)node * 96 + j0;
        #pragma unroll
        for (int p = 0; p < 6; p++) {
            float2 v = unpack2(acc[r][p]);
            float2 y = *(const float2*)&yr[2 * p];
            float2 s;
            s.x = fmaxf(v.x + y.x, 0.f);
            s.y = fmaxf(v.y + y.y, 0.f);
            *(float2*)&h2b[row][j0 + 2 * p] = s;
        }
        #pragma unroll
        for (int p = 0; p < 6; p++) acc[r][p] = 0ull;
    }

    // phase B: g_y = [h2@Wl2 | h2@Wr2 + b2]
    for (int kc = 0; kc < 96; kc += KC) {
        __syncthreads();
        #pragma unroll
        for (int idx = tid; idx < KC * 24; idx += 128) {
            int kk = idx / 24, j4 = idx % 24;
            int j = j4 * 4;
            float4 v = (j < 48) ? *(const float4*)&Wl2[(kc + kk) * 48 + j]
                                : *(const float4*)&Wr2[(kc + kk) * 48 + (j - 48)];
            *(float4*)&sW[kk][j] = v;
        }
        __syncthreads();

        #pragma unroll 2
        for (int k = 0; k < KC; k++) {
            ull w[6];
            #pragma unroll
            for (int p = 0; p < 6; p++) {
                float2 l = *(const float2*)&sW[k][j0 + 2 * p];
                w[p] = pack2(l.x, l.y);
            }
            #pragma unroll
            for (int r = 0; r < 4; r++) {
                float hv = h2b[ig * 4 + r][kc + k];
                ull a2 = pack2(hv, hv);
                #pragma unroll
                for (int p = 0; p < 6; p++)
                    acc[r][p] = fma2(a2, w[p], acc[r][p]);
            }
        }
    }

    #pragma unroll
    for (int r = 0; r < 4; r++) {
        int node = node0 + ig * 4 + r;
        if (node < N_NODES) {
            float* o = g_y + (size_t)node * 96 + j0;
            #pragma unroll
            for (int p = 0; p < 6; p++) {
                float2 v = unpack2(acc[r][p]);
                int c = j0 + 2 * p;
                if (c >= 48) { v.x += b2[c - 48]; v.y += b2[c - 47]; }
                *(float2*)&o[2 * p] = v;
            }
        }
    }
}

// ---- final 48-wide aggregation + relu (R8 verbatim) ----------------------------
__global__ void k_agg48(float* __restrict__ out) {
    int w    = (blockIdx.x * blockDim.x + threadIdx.x) >> 5;
    int lane = threadIdx.x & 31;
    if (w >= N_NODES) return;
    int beg = g_off[w], end = g_off[w + 1];
    float a0 = 0.f, a1 = 0.f, b0 = 0.f, b1 = 0.f;
    int e = beg;
    for (; e + 7 < end; e += 8) {
        const float* r0 = g_y + (size_t)g_esrc[e]     * 96;
        const float* r1 = g_y + (size_t)g_esrc[e + 1] * 96;
        const float* r2 = g_y + (size_t)g_esrc[e + 2] * 96;
        const float* r3 = g_y + (size_t)g_esrc[e + 3] * 96;
        const float* r4 = g_y + (size_t)g_esrc[e + 4] * 96;
        const float* r5 = g_y + (size_t)g_esrc[e + 5] * 96;
        const float* r6 = g_y + (size_t)g_esrc[e + 6] * 96;
        const float* r7 = g_y + (size_t)g_esrc[e + 7] * 96;
        a0 += (r0[lane] + r1[lane]) + (r2[lane] + r3[lane]);
        b0 += (r4[lane] + r5[lane]) + (r6[lane] + r7[lane]);
        if (lane < 16) {
            a1 += (r0[32+lane] + r1[32+lane]) + (r2[32+lane] + r3[32+lane]);
            b1 += (r4[32+lane] + r5[32+lane]) + (r6[32+lane] + r7[32+lane]);
        }
    }
    for (; e < end; e++) {
        const float* r0 = g_y + (size_t)g_esrc[e] * 96;
        a0 += r0[lane];
        if (lane < 16) a1 += r0[32 + lane];
    }
    a0 += b0; a1 += b1;
    int deg = end - beg;
    float inv = 1.0f / (float)(deg > 0 ? deg : 1);
    const float* yr = g_y + (size_t)w * 96 + 48;
    float* o = out + (size_t)w * 48;
    o[lane] = fmaxf(a0 * inv + yr[lane], 0.f);
    if (lane < 16) o[32 + lane] = fmaxf(a1 * inv + yr[32 + lane], 0.f);
}

// ---------------- launch: two-branch graph via stream fork/join -----------------
extern "C" void kernel_launch(void* const* d_in, const int* in_sizes, int n_in,
                              void* d_out, int out_size)
{
    const float* x   = (const float*)d_in[0];
    const int*   ei  = (const int*)d_in[1];     // int32 (JAX x64 disabled)
    const float* Wl0 = (const float*)d_in[2];
    const float* Wr0 = (const float*)d_in[3];
    const float* b0  = (const float*)d_in[4];
    const float* Wl1 = (const float*)d_in[5];
    const float* Wr1 = (const float*)d_in[6];
    const float* b1  = (const float*)d_in[7];
    const float* Wl2 = (const float*)d_in[8];
    const float* Wr2 = (const float*)d_in[9];
    const float* b2  = (const float*)d_in[10];
    float*       out = (float*)d_out;

    // side stream + events, created once (first call = correctness run,
    // before graph capture; capture replays identical topology every call)
    static cudaStream_t s1 = nullptr;
    static cudaEvent_t ev0, ev1, ev2, ev3;
    if (!s1) {
        cudaStreamCreateWithFlags(&s1, cudaStreamNonBlocking);
        cudaEventCreateWithFlags(&ev0, cudaEventDisableTiming);
        cudaEventCreateWithFlags(&ev1, cudaEventDisableTiming);
        cudaEventCreateWithFlags(&ev2, cudaEventDisableTiming);
        cudaEventCreateWithFlags(&ev3, cudaEventDisableTiming);
    }

    const int nScanBlk = (N_NODES + 1023) / 1024;   // 49
    const int nEdgeBlk = (N_EDGES + 255) / 256;     // 3125
    const int aggBlk   = (N_NODES + 7) / 8;         // 6250
    const int tileBlk  = (N_NODES + 63) / 64;       // 782

    // fork: gemmR0 on side stream (depends only on x)
    cudaEventRecord(ev0, 0);
    cudaStreamWaitEvent(s1, ev0, 0);
    k_gemmR<0><<<tileBlk, 128, 0, s1>>>(x, Wr0, b0);
    cudaEventRecord(ev1, s1);

    // main branch: CSR build + agg0
    k_zero<<<(N_NODES + 255) / 256, 256>>>();
    k_count<<<nEdgeBlk, 256>>>(ei);
    k_scan1<<<nScanBlk, 1024>>>();
    k_scan3<<<nScanBlk, 1024>>>();
    k_fill<<<nEdgeBlk, 256>>>(ei);
    k_agg<0><<<aggBlk, 256>>>(x);

    // join gemmR0, then gemmL0 -> h1
    cudaStreamWaitEvent(0, ev1, 0);
    k_gemmL0<<<tileBlk, 128>>>(Wl0);

    // fork: gemmR1 (reads h1) concurrent with agg1 (reads h1)
    cudaEventRecord(ev2, 0);
    cudaStreamWaitEvent(s1, ev2, 0);
    k_gemmR<1><<<tileBlk, 128, 0, s1>>>(nullptr, Wr1, b1);
    cudaEventRecord(ev3, s1);

    k_agg<1><<<aggBlk, 256>>>(nullptr);

    // join gemmR1, then gemmL1 + layer2 projection, final aggregation
    cudaStreamWaitEvent(0, ev3, 0);
    k_gemmL1_proj<<<tileBlk, 128>>>(Wl1, Wl2, Wr2, b2);
    k_agg48<<<aggBlk, 256>>>(out);
}